// round 3
// baseline (speedup 1.0000x reference)
#include <cuda_runtime.h>
#include <cuda_bf16.h>
#include <cstdint>
#include <math.h>

#define DEV_INLINE __device__ __forceinline__

// Does this compilation pass target sm_103a (arch-specific features available)?
#ifdef __CUDA_ARCH_FEAT_SM103_ALL
#define USE_TC 1
#else
#define USE_TC 0
#endif

// ---------------- problem constants ----------------
#define B_DIM 4096          // batch rows (GEMM M)
#define K_DIM 2048          // inner dim  (GEMM K)
#define M_DIM 2048          // out cols   (GEMM N)

// ---------------- GEMM tiling (both paths: CTA covers 128 x 256) ----------------
#define BM 128
#define BN 256
#define THREADS 512

// ---- tcgen05 path smem ----
#define SMEM_TMEM_PTR 0
#define SMEM_MBAR0    8
#define SMEM_MBAR1    16
#define TILE_BASE     1024
#define TC_BK         64
#define TC_NT         (K_DIM / TC_BK)              // 32
#define A_BYTES       (BM * 128)                   // 16384
#define B_BYTES       (BN * 128)                   // 32768
#define STAGE_BYTES   (2 * A_BYTES + 2 * B_BYTES)  // 98304
#define SMEM_TOTAL    (TILE_BASE + 2 * STAGE_BYTES)// 197632

// ---- hmma fallback smem ----
#define MM_BK         32
#define MM_NT         (K_DIM / MM_BK)              // 64
#define MM_ROWB       80                           // 64B row + 16B pad
#define MM_A_BYTES    (BM * MM_ROWB)               // 10240
#define MM_B_BYTES    (BN * MM_ROWB)               // 20480
#define MM_STAGE      (2 * MM_A_BYTES + 2 * MM_B_BYTES)  // 61440
#define MM_STAGES     3
// 1024 + 3*61440 = 185344 <= SMEM_TOTAL ✓

// ---------------- device scratch (allocation-free rule: __device__ globals) ----------------
__device__ __align__(16) __nv_bfloat16 g_xh[(long)B_DIM * K_DIM];
__device__ __align__(16) __nv_bfloat16 g_xl[(long)B_DIM * K_DIM];
__device__ __align__(16) __nv_bfloat16 g_wh[(long)M_DIM * K_DIM];   // [j][k] (transposed W)
__device__ __align__(16) __nv_bfloat16 g_wl[(long)M_DIM * K_DIM];
__device__ float g_bias[M_DIM];                                     // classical_bias + probs

// ---------------- PTX helpers (base-arch legal) ----------------
DEV_INLINE uint32_t smem_u32(const void* p) {
    uint32_t a;
    asm("{ .reg .u64 t; cvta.to.shared.u64 t, %1; cvt.u32.u64 %0, t; }" : "=r"(a) : "l"(p));
    return a;
}
#define SWZ128(o) ((o) ^ (((o) >> 3) & 0x70))

DEV_INLINE void cp16(uint32_t dst, const void* src) {
    asm volatile("cp.async.cg.shared.global [%0], [%1], 16;" :: "r"(dst), "l"(src) : "memory");
}
DEV_INLINE void cp_commit() { asm volatile("cp.async.commit_group;" ::: "memory"); }

DEV_INLINE void ldsm4(uint32_t* r, uint32_t addr) {
    asm volatile("ldmatrix.sync.aligned.m8n8.x4.shared.b16 {%0,%1,%2,%3}, [%4];"
                 : "=r"(r[0]), "=r"(r[1]), "=r"(r[2]), "=r"(r[3]) : "r"(addr));
}
DEV_INLINE void mma16816(float* c, const uint32_t* a, uint32_t b0, uint32_t b1) {
    asm volatile("mma.sync.aligned.m16n8k16.row.col.f32.bf16.bf16.f32 "
                 "{%0,%1,%2,%3}, {%4,%5,%6,%7}, {%8,%9}, {%0,%1,%2,%3};"
                 : "+f"(c[0]), "+f"(c[1]), "+f"(c[2]), "+f"(c[3])
                 : "r"(a[0]), "r"(a[1]), "r"(a[2]), "r"(a[3]), "r"(b0), "r"(b1));
}

#if USE_TC
// ---------------- tcgen05 helpers (only compiled in the sm_103a pass) ----------------
DEV_INLINE uint32_t elect_one() {
    uint32_t pred;
    asm volatile("{\n\t.reg .pred p;\n\telect.sync _|p, 0xFFFFFFFF;\n\t"
                 "selp.b32 %0, 1, 0, p;\n\t}" : "=r"(pred));
    return pred;
}
#define MBAR_INIT(addr, cnt) \
    asm volatile("mbarrier.init.shared.b64 [%0], %1;" :: "r"(addr), "r"(cnt) : "memory")
#define MBAR_INVAL(addr) \
    asm volatile("mbarrier.inval.shared.b64 [%0];" :: "r"(addr) : "memory")

DEV_INLINE void mbar_wait(uint32_t mbar, uint32_t parity) {
    uint32_t done;
    asm volatile("{\n\t.reg .pred p;\n\t"
                 "mbarrier.try_wait.parity.acquire.cta.shared::cta.b64 p, [%1], %2;\n\t"
                 "selp.b32 %0, 1, 0, p;\n\t}"
                 : "=r"(done) : "r"(mbar), "r"(parity) : "memory");
    if (!done) {
        asm volatile("{\n\t.reg .pred P1;\n\t"
                     "W_%=:\n\t"
                     "mbarrier.try_wait.parity.acquire.cta.shared::cta.b64 P1, [%0], %1, 0x989680;\n\t"
                     "@P1 bra.uni D_%=;\n\t"
                     "bra.uni W_%=;\n\t"
                     "D_%=:\n\t}"
                     :: "r"(mbar), "r"(parity) : "memory");
    }
}

#define TCGEN05_ALLOC(sm_addr, nc) \
    asm volatile("tcgen05.alloc.cta_group::1.sync.aligned.shared::cta.b32 [%0], %1;" \
                 :: "r"((uint32_t)(sm_addr)), "r"((uint32_t)(nc)) : "memory")
#define TCGEN05_DEALLOC(tmem, nc) \
    asm volatile("tcgen05.dealloc.cta_group::1.sync.aligned.b32 %0, %1;" :: "r"(tmem), "r"(nc))
#define TCGEN05_COMMIT(mbar) \
    asm volatile("tcgen05.commit.cta_group::1.mbarrier::arrive::one.shared::cluster.b64 [%0];" \
                 :: "r"((uint32_t)(mbar)) : "memory")
#define TCGEN05_FENCE_AFTER()  asm volatile("tcgen05.fence::after_thread_sync;" ::: "memory")
#define TCGEN05_FENCE_BEFORE() asm volatile("tcgen05.fence::before_thread_sync;" ::: "memory")
#define TCGEN05_WAIT_LD()      asm volatile("tcgen05.wait::ld.sync.aligned;" ::: "memory")

#define TCGEN05_LD_X32(r, ta) \
    asm volatile("tcgen05.ld.sync.aligned.32x32b.x32.b32 " \
        "{%0, %1, %2, %3, %4, %5, %6, %7, %8, %9, %10, %11, %12, %13, %14, %15, " \
        " %16, %17, %18, %19, %20, %21, %22, %23, %24, %25, %26, %27, %28, %29, %30, %31}, [%32];" \
        : "=r"((r)[0]),  "=r"((r)[1]),  "=r"((r)[2]),  "=r"((r)[3]), \
          "=r"((r)[4]),  "=r"((r)[5]),  "=r"((r)[6]),  "=r"((r)[7]), \
          "=r"((r)[8]),  "=r"((r)[9]),  "=r"((r)[10]), "=r"((r)[11]), \
          "=r"((r)[12]), "=r"((r)[13]), "=r"((r)[14]), "=r"((r)[15]), \
          "=r"((r)[16]), "=r"((r)[17]), "=r"((r)[18]), "=r"((r)[19]), \
          "=r"((r)[20]), "=r"((r)[21]), "=r"((r)[22]), "=r"((r)[23]), \
          "=r"((r)[24]), "=r"((r)[25]), "=r"((r)[26]), "=r"((r)[27]), \
          "=r"((r)[28]), "=r"((r)[29]), "=r"((r)[30]), "=r"((r)[31]) \
        : "r"(ta))

static constexpr uint64_t DESC_BASE =
    (uint64_t(2) << 61) | (uint64_t(1) << 46) | (uint64_t(64) << 32) | (uint64_t(1) << 16);
DEV_INLINE uint64_t make_desc(uint32_t addr) {
    return DESC_BASE | ((uint64_t)(addr >> 4) & 0x3FFF);
}
// idesc kind::f16: fp32 acc, bf16 A, bf16 B, M=128, N=128
#define MMA_IDESC ((1u << 4) | (1u << 7) | (1u << 10) | ((128u / 8u) << 17) | ((128u / 16u) << 24))

DEV_INLINE void mma_bf16_ss(uint32_t d_tmem, uint64_t a_desc, uint64_t b_desc, uint32_t en) {
    asm volatile("{\n\t.reg .pred p;\n\tsetp.ne.u32 p, %4, 0;\n\t"
                 "tcgen05.mma.cta_group::1.kind::f16 [%0], %1, %2, %3, {%5, %5, %5, %5}, p;\n\t}"
                 :: "r"(d_tmem), "l"(a_desc), "l"(b_desc), "r"(MMA_IDESC),
                    "r"(en), "r"(0u)
                 : "memory");
}
#endif // USE_TC

// ---------------- split helpers ----------------
DEV_INLINE void split1(float v, __nv_bfloat16& h, __nv_bfloat16& l) {
    h = __float2bfloat16(v);
    l = __float2bfloat16(v - __bfloat162float(h));
}

// ---------------- prep kernel 1: split x into bf16 hi/lo ----------------
__global__ void split_x_kernel(const float* __restrict__ x) {
    long i = ((long)blockIdx.x * blockDim.x + threadIdx.x) * 4;
    float4 v = *(const float4*)(x + i);
    __nv_bfloat16 h0, h1, h2, h3, l0, l1, l2, l3;
    split1(v.x, h0, l0); split1(v.y, h1, l1); split1(v.z, h2, l2); split1(v.w, h3, l3);
    ushort4 hv, lv;
    hv.x = __bfloat16_as_ushort(h0); hv.y = __bfloat16_as_ushort(h1);
    hv.z = __bfloat16_as_ushort(h2); hv.w = __bfloat16_as_ushort(h3);
    lv.x = __bfloat16_as_ushort(l0); lv.y = __bfloat16_as_ushort(l1);
    lv.z = __bfloat16_as_ushort(l2); lv.w = __bfloat16_as_ushort(l3);
    *(ushort4*)((unsigned short*)g_xh + i) = hv;
    *(ushort4*)((unsigned short*)g_xl + i) = lv;
}

// ---------------- prep kernel 2: transpose-split W -> wh/wl [j][k] ----------------
__global__ void split_w_kernel(const float* __restrict__ W) {   // W[k][j] row-major
    __shared__ float t[32][33];
    int j0 = blockIdx.x * 32, k0 = blockIdx.y * 32;
    int tx = threadIdx.x, ty = threadIdx.y;   // block (32, 8)
#pragma unroll
    for (int r = ty; r < 32; r += 8)
        t[r][tx] = W[(long)(k0 + r) * M_DIM + j0 + tx];
    __syncthreads();
#pragma unroll
    for (int r = ty; r < 32; r += 8) {
        float v = t[tx][r];                   // = W[k0+tx][j0+r]
        __nv_bfloat16 h, l; split1(v, h, l);
        long o = (long)(j0 + r) * K_DIM + k0 + tx;
        g_wh[o] = h; g_wl[o] = l;
    }
}

// ---------------- prep kernel 3: probs + bias fold ----------------
// probs[j] = (1/K_DIM) * prod_{d<9,g<3} cos^2(E[d, j, g])   (state stays row-constant)
__global__ void probs_kernel(const float* __restrict__ E, const float* __restrict__ cb) {
    int j = blockIdx.x * blockDim.x + threadIdx.x;
    if (j >= M_DIM) return;
    float p = 1.0f;
#pragma unroll
    for (int d = 0; d < 9; d++) {
#pragma unroll
        for (int g = 0; g < 3; g++) {
            float a = E[(long)d * K_DIM * M_DIM + (long)j * M_DIM + g];
            float c = cosf(a);
            p *= c * c;
        }
    }
    g_bias[j] = cb[j] + p * (1.0f / (float)K_DIM);
}

#if USE_TC
// ---------------- tcgen05 tile loader (SW128, BK=64) ----------------
DEV_INLINE void load_tile_tc(uint32_t smem_base, int stage, int kt, int tileM, int tileN, int tid) {
    uint32_t sa = smem_base + TILE_BASE + stage * STAGE_BYTES;
    long krow = (long)kt * TC_BK * 2;   // byte offset within a K-row (bf16)
    const char* xh = (const char*)g_xh;
    const char* xl = (const char*)g_xl;
    const char* wh = (const char*)g_wh;
    const char* wl = (const char*)g_wl;
#pragma unroll
    for (int i = tid; i < BM * 8; i += THREADS) {          // A: 128 rows x 8 chunks of 16B
        int r = i >> 3, c = i & 7;
        uint32_t off = SWZ128(r * 128 + c * 16);
        long gb = ((long)(tileM * BM + r) * K_DIM) * 2 + krow + c * 16;
        cp16(sa + off, xh + gb);
        cp16(sa + A_BYTES + off, xl + gb);
    }
#pragma unroll
    for (int i = tid; i < BN * 8; i += THREADS) {          // B: 256 rows x 8 chunks of 16B
        int r = i >> 3, c = i & 7;
        uint32_t off = SWZ128(r * 128 + c * 16);
        long gb = ((long)(tileN * BN + r) * K_DIM) * 2 + krow + c * 16;
        cp16(sa + 2 * A_BYTES + off, wh + gb);
        cp16(sa + 2 * A_BYTES + B_BYTES + off, wl + gb);
    }
    cp_commit();
}
#else
// ---------------- hmma tile loader (padded rows, BK=32) ----------------
DEV_INLINE void load_tile_mm(uint32_t smem_base, int stage, int kt, int tileM, int tileN, int tid) {
    uint32_t sb = smem_base + TILE_BASE + stage * MM_STAGE;
#pragma unroll
    for (int i = tid; i < 3072; i += THREADS) {
        if (i < 1024) {                                   // A hi (512) then A lo (512)
            int hl = i >> 9;
            int t = i & 511; int r = t >> 2, c = t & 3;
            uint32_t dst = sb + hl * MM_A_BYTES + r * MM_ROWB + c * 16;
            long src = (long)(tileM * BM + r) * (K_DIM * 2) + (long)kt * (MM_BK * 2) + c * 16;
            cp16(dst, (const char*)(hl ? (const void*)g_xl : (const void*)g_xh) + src);
        } else {                                          // B hi (1024) then B lo (1024)
            int j = i - 1024; int hl = j >> 10;
            int t = j & 1023; int r = t >> 2, c = t & 3;
            uint32_t dst = sb + 2 * MM_A_BYTES + hl * MM_B_BYTES + r * MM_ROWB + c * 16;
            long src = (long)(tileN * BN + r) * (K_DIM * 2) + (long)kt * (MM_BK * 2) + c * 16;
            cp16(dst, (const char*)(hl ? (const void*)g_wl : (const void*)g_wh) + src);
        }
    }
    cp_commit();
}
#endif

// ---------------- main GEMM: fused tanh epilogue, dual path ----------------
__global__ void __launch_bounds__(THREADS, 1)
gemm_kernel(float* __restrict__ out) {
    extern __shared__ char smem[];
    uint32_t smem_base = smem_u32(smem);
    int tid = threadIdx.x;
    int wid = tid >> 5, lid = tid & 31;
    int bid = blockIdx.x;
    int tileM = bid & 31;   // consecutive CTAs share the W band -> L2 reuse
    int tileN = bid >> 5;   // 0..7

#if USE_TC
    // ================= tcgen05 path =================
    if (wid == 0) TCGEN05_ALLOC(smem_base + SMEM_TMEM_PTR, 256);
    if (tid == 0) {
        MBAR_INIT(smem_base + SMEM_MBAR0, 1);
        MBAR_INIT(smem_base + SMEM_MBAR1, 1);
    }
    __syncthreads();
    uint32_t tmem;
    asm volatile("ld.shared.b32 %0, [%1];" : "=r"(tmem) : "r"(smem_base + SMEM_TMEM_PTR));

    load_tile_tc(smem_base, 0, 0, tileM, tileN, tid);
    load_tile_tc(smem_base, 1, 1, tileM, tileN, tid);

    uint32_t epred = elect_one();
    uint32_t phase0 = 0, phase1 = 0;

    for (int kt = 0; kt < TC_NT; ++kt) {
        int s = kt & 1;
        if (kt == TC_NT - 1) asm volatile("cp.async.wait_group 0;" ::: "memory");
        else                 asm volatile("cp.async.wait_group 1;" ::: "memory");
        __syncthreads();
        asm volatile("fence.proxy.async.shared::cta;" ::: "memory");

        if (wid == 0 && epred) {
            uint32_t sa  = smem_base + TILE_BASE + s * STAGE_BYTES;
            uint64_t dah = make_desc(sa);
            uint64_t dal = make_desc(sa + A_BYTES);
            uint64_t dbh = make_desc(sa + 2 * A_BYTES);
            uint64_t dbl = make_desc(sa + 2 * A_BYTES + B_BYTES);
#pragma unroll
            for (int ks = 0; ks < 4; ++ks) {               // K=16 per MMA
                uint64_t o = (uint64_t)(ks * 2);
#pragma unroll
                for (int h = 0; h < 2; ++h) {              // two N=128 halves
                    uint64_t bo = o + (uint64_t)h * 1024;  // 128 rows * 128B = 1024 units
                    uint32_t dd = tmem + h * 128;
                    uint32_t acc = (kt > 0) || (ks > 0);
                    mma_bf16_ss(dd, dah + o, dbh + bo, acc);  // hi*hi
                    mma_bf16_ss(dd, dah + o, dbl + bo, 1u);   // hi*lo
                    mma_bf16_ss(dd, dal + o, dbh + bo, 1u);   // lo*hi
                }
            }
            TCGEN05_COMMIT(smem_base + (s ? SMEM_MBAR1 : SMEM_MBAR0));
        }

        if (s == 0) { mbar_wait(smem_base + SMEM_MBAR0, phase0); phase0 ^= 1; }
        else        { mbar_wait(smem_base + SMEM_MBAR1, phase1); phase1 ^= 1; }

        if (kt + 2 < TC_NT)
            load_tile_tc(smem_base, s, kt + 2, tileM, tileN, tid);
    }

    __syncthreads();
    TCGEN05_FENCE_AFTER();

    // Epilogue: 16 warps. warp w -> TMEM rows (w%4)*32 (its subpartition), cols (w/4)*64
    {
        int rrow  = (wid & 3) * 32 + lid;
        long gm   = (long)tileM * BM + rrow;
        int cbase = (wid >> 2) * 64;
#pragma unroll
        for (int cc = 0; cc < 2; ++cc) {
            uint32_t d[32];
            TCGEN05_LD_X32(d, tmem + cbase + cc * 32);
            TCGEN05_WAIT_LD();
            int gc = tileN * BN + cbase + cc * 32;
            const float4* bp = (const float4*)(g_bias + gc);
            float4* op = (float4*)(out + gm * M_DIM + gc);
#pragma unroll
            for (int q = 0; q < 8; ++q) {
                float4 b = bp[q];
                float4 o;
                o.x = tanhf(__uint_as_float(d[q * 4 + 0]) + b.x);
                o.y = tanhf(__uint_as_float(d[q * 4 + 1]) + b.y);
                o.z = tanhf(__uint_as_float(d[q * 4 + 2]) + b.z);
                o.w = tanhf(__uint_as_float(d[q * 4 + 3]) + b.w);
                op[q] = o;
            }
        }
        TCGEN05_FENCE_BEFORE();
    }

    __syncthreads();
    if (tid == 0) { MBAR_INVAL(smem_base + SMEM_MBAR0); MBAR_INVAL(smem_base + SMEM_MBAR1); }
    __syncthreads();
    if (wid == 0) TCGEN05_DEALLOC(tmem, 256);

#else
    // ================= HMMA fallback (base-PTX legal) =================
    // 16 warps, 4(m) x 4(n); warp tile 32 x 64; BK=32, 3-stage cp.async pipeline.
    int wr = wid & 3;        // warp row: 32 rows each
    int wc = wid >> 2;       // warp col: 64 cols each

    float acc[2][8][4];
#pragma unroll
    for (int mt = 0; mt < 2; ++mt)
#pragma unroll
        for (int nt = 0; nt < 8; ++nt)
#pragma unroll
            for (int q = 0; q < 4; ++q) acc[mt][nt][q] = 0.0f;

    load_tile_mm(smem_base, 0, 0, tileM, tileN, tid);
    load_tile_mm(smem_base, 1, 1, tileM, tileN, tid);
    load_tile_mm(smem_base, 2, 2, tileM, tileN, tid);

    const int lrow = lid & 15;
    const int lk16b = (lid >> 4) * 16;    // 0 or 16 bytes (k halves for ldmatrix.x4)

    for (int kt = 0; kt < MM_NT; ++kt) {
        asm volatile("cp.async.wait_group 2;" ::: "memory");
        __syncthreads();

        int s = kt % MM_STAGES;
        uint32_t sb  = smem_base + TILE_BASE + s * MM_STAGE;
        uint32_t sAh = sb;
        uint32_t sAl = sb + MM_A_BYTES;
        uint32_t sBh = sb + 2 * MM_A_BYTES;
        uint32_t sBl = sb + 2 * MM_A_BYTES + MM_B_BYTES;

#pragma unroll
        for (int k16 = 0; k16 < 2; ++k16) {
            uint32_t koff = k16 * 32 + lk16b;
            uint32_t aoff = (uint32_t)(wr * 32 + lrow) * MM_ROWB + koff;
            uint32_t boff = (uint32_t)(wc * 64 + lrow) * MM_ROWB + koff;

            uint32_t ah[2][4], bh[4][4];
            ldsm4(ah[0], sAh + aoff);
            ldsm4(ah[1], sAh + aoff + 16 * MM_ROWB);
#pragma unroll
            for (int g = 0; g < 4; ++g) ldsm4(bh[g], sBh + boff + g * 16 * MM_ROWB);

#pragma unroll
            for (int mt = 0; mt < 2; ++mt)
#pragma unroll
                for (int nt = 0; nt < 8; ++nt)
                    mma16816(acc[mt][nt], ah[mt], bh[nt >> 1][nt & 1], bh[nt >> 1][(nt & 1) + 2]);

            uint32_t al[2][4];
            ldsm4(al[0], sAl + aoff);
            ldsm4(al[1], sAl + aoff + 16 * MM_ROWB);
#pragma unroll
            for (int mt = 0; mt < 2; ++mt)
#pragma unroll
                for (int nt = 0; nt < 8; ++nt)
                    mma16816(acc[mt][nt], al[mt], bh[nt >> 1][nt & 1], bh[nt >> 1][(nt & 1) + 2]);

            uint32_t bl[4][4];
#pragma unroll
            for (int g = 0; g < 4; ++g) ldsm4(bl[g], sBl + boff + g * 16 * MM_ROWB);
#pragma unroll
            for (int mt = 0; mt < 2; ++mt)
#pragma unroll
                for (int nt = 0; nt < 8; ++nt)
                    mma16816(acc[mt][nt], ah[mt], bl[nt >> 1][nt & 1], bl[nt >> 1][(nt & 1) + 2]);
        }

        __syncthreads();
        if (kt + MM_STAGES < MM_NT)
            load_tile_mm(smem_base, s, kt + MM_STAGES, tileM, tileN, tid);
    }

    // Epilogue: tanh(acc + bias), direct from registers
    {
        int r0 = tileM * BM + wr * 32 + (lid >> 2);
        int c0 = tileN * BN + wc * 64 + (lid & 3) * 2;
#pragma unroll
        for (int mt = 0; mt < 2; ++mt) {
#pragma unroll
            for (int nt = 0; nt < 8; ++nt) {
                int row = r0 + mt * 16;
                int col = c0 + nt * 8;
                float2 bv = *(const float2*)(g_bias + col);
                float2 o0, o1;
                o0.x = tanhf(acc[mt][nt][0] + bv.x);
                o0.y = tanhf(acc[mt][nt][1] + bv.y);
                o1.x = tanhf(acc[mt][nt][2] + bv.x);
                o1.y = tanhf(acc[mt][nt][3] + bv.y);
                *(float2*)(out + (long)row * M_DIM + col) = o0;
                *(float2*)(out + (long)(row + 8) * M_DIM + col) = o1;
            }
        }
    }
#endif
}

// ---------------- launch ----------------
extern "C" void kernel_launch(void* const* d_in, const int* in_sizes, int n_in,
                              void* d_out, int out_size) {
    const float* x  = (const float*)d_in[0];
    const float* E  = (const float*)d_in[1];
    // d_in[2] = eternal_biases: unused by the reference as well
    const float* W  = (const float*)d_in[3];
    const float* cb = (const float*)d_in[4];
    float* out = (float*)d_out;

    cudaFuncSetAttribute(gemm_kernel, cudaFuncAttributeMaxDynamicSharedMemorySize, SMEM_TOTAL);

    split_x_kernel<<<(int)(((long)B_DIM * K_DIM / 4) / 256), 256>>>(x);
    split_w_kernel<<<dim3(M_DIM / 32, K_DIM / 32), dim3(32, 8)>>>(W);
    probs_kernel<<<M_DIM / 256, 256>>>(E, cb);
    gemm_kernel<<<(B_DIM / BM) * (M_DIM / BN), THREADS, SMEM_TOTAL>>>(out);
}

// round 5
// speedup vs baseline: 1.2334x; 1.2334x over previous
#include <cuda_runtime.h>
#include <cuda.h>
#include <cuda_bf16.h>
#include <cstdint>
#include <math.h>

#define DEV_INLINE __device__ __forceinline__

// Does this compilation pass target sm_103a (arch-specific features available)?
#ifdef __CUDA_ARCH_FEAT_SM103_ALL
#define USE_TC 1
#else
#define USE_TC 0
#endif

// ---------------- problem constants ----------------
#define B_DIM 4096          // batch rows (GEMM M)
#define K_DIM 2048          // inner dim  (GEMM K)
#define M_DIM 2048          // out cols   (GEMM N)

// ---------------- GEMM tiling (both paths: CTA covers 128 x 256) ----------------
#define BM 128
#define BN 256
#define THREADS 512
#define CLUSTER_SZ 2

// ---- tcgen05 path smem ----
#define SMEM_TMEM_PTR 0
#define SMEM_FULL0    8
#define SMEM_FULL1    16
#define SMEM_DONE0    24
#define SMEM_DONE1    32
#define SMEM_FINAL    40
#define TILE_BASE     1024
#define TC_BK         64
#define TC_NT         (K_DIM / TC_BK)              // 32
#define A_BYTES       (BM * 128)                   // 16384 (Ah or Al tile)
#define B_BYTES       (BN * 128)                   // 32768 (Bh or Bl tile)
#define STAGE_BYTES   (2 * A_BYTES + 2 * B_BYTES)  // 98304
#define SMEM_TOTAL    (TILE_BASE + 2 * STAGE_BYTES)// 197632

// ---- hmma fallback smem (compile-legality for the compute_103 PTX pass) ----
#define MM_BK         32
#define MM_NT         (K_DIM / MM_BK)              // 64
#define MM_ROWB       80                           // 64B row + 16B pad
#define MM_A_BYTES    (BM * MM_ROWB)               // 10240
#define MM_B_BYTES    (BN * MM_ROWB)               // 20480
#define MM_STAGE      (2 * MM_A_BYTES + 2 * MM_B_BYTES)  // 61440
#define MM_STAGES     3

// ---------------- device scratch (allocation-free rule: __device__ globals) ----------------
__device__ __align__(16) __nv_bfloat16 g_xh[(long)B_DIM * K_DIM];
__device__ __align__(16) __nv_bfloat16 g_xl[(long)B_DIM * K_DIM];
__device__ __align__(16) __nv_bfloat16 g_wh[(long)M_DIM * K_DIM];   // [j][k] (transposed W)
__device__ __align__(16) __nv_bfloat16 g_wl[(long)M_DIM * K_DIM];
__device__ float g_bias[M_DIM];                                     // classical_bias + probs

// ---------------- PTX helpers (base-arch legal) ----------------
DEV_INLINE uint32_t smem_u32(const void* p) {
    uint32_t a;
    asm("{ .reg .u64 t; cvta.to.shared.u64 t, %1; cvt.u32.u64 %0, t; }" : "=r"(a) : "l"(p));
    return a;
}
#define SWZ128(o) ((o) ^ (((o) >> 3) & 0x70))

DEV_INLINE void cp16(uint32_t dst, const void* src) {
    asm volatile("cp.async.cg.shared.global [%0], [%1], 16;" :: "r"(dst), "l"(src) : "memory");
}
DEV_INLINE void cp_commit() { asm volatile("cp.async.commit_group;" ::: "memory"); }

DEV_INLINE void ldsm4(uint32_t* r, uint32_t addr) {
    asm volatile("ldmatrix.sync.aligned.m8n8.x4.shared.b16 {%0,%1,%2,%3}, [%4];"
                 : "=r"(r[0]), "=r"(r[1]), "=r"(r[2]), "=r"(r[3]) : "r"(addr));
}
DEV_INLINE void mma16816(float* c, const uint32_t* a, uint32_t b0, uint32_t b1) {
    asm volatile("mma.sync.aligned.m16n8k16.row.col.f32.bf16.bf16.f32 "
                 "{%0,%1,%2,%3}, {%4,%5,%6,%7}, {%8,%9}, {%0,%1,%2,%3};"
                 : "+f"(c[0]), "+f"(c[1]), "+f"(c[2]), "+f"(c[3])
                 : "r"(a[0]), "r"(a[1]), "r"(a[2]), "r"(a[3]), "r"(b0), "r"(b1));
}

#if USE_TC
// ---------------- tcgen05 / TMA helpers (only in the sm_103a pass) ----------------
DEV_INLINE uint32_t elect_one() {
    uint32_t pred;
    asm volatile("{\n\t.reg .pred p;\n\telect.sync _|p, 0xFFFFFFFF;\n\t"
                 "selp.b32 %0, 1, 0, p;\n\t}" : "=r"(pred));
    return pred;
}
DEV_INLINE uint32_t ctarank() {
    uint32_t r;
    asm("mov.u32 %0, %%cluster_ctarank;" : "=r"(r));
    return r;
}
#define MBAR_INIT(addr, cnt) \
    asm volatile("mbarrier.init.shared.b64 [%0], %1;" :: "r"(addr), "r"(cnt) : "memory")
#define MBAR_INVAL(addr) \
    asm volatile("mbarrier.inval.shared.b64 [%0];" :: "r"(addr) : "memory")
#define MBAR_EXPECT_TX(addr, tx) \
    asm volatile("mbarrier.arrive.expect_tx.shared.b64 _, [%0], %1;" \
                 :: "r"(addr), "r"((uint32_t)(tx)) : "memory")
#define CLUSTER_SYNC() do { \
    asm volatile("barrier.cluster.arrive.aligned;" ::: "memory"); \
    asm volatile("barrier.cluster.wait.aligned;" ::: "memory"); \
} while (0)

DEV_INLINE void mbar_wait(uint32_t mbar, uint32_t parity) {
    uint32_t done;
    asm volatile("{\n\t.reg .pred p;\n\t"
                 "mbarrier.try_wait.parity.acquire.cta.shared::cta.b64 p, [%1], %2;\n\t"
                 "selp.b32 %0, 1, 0, p;\n\t}"
                 : "=r"(done) : "r"(mbar), "r"(parity) : "memory");
    if (!done) {
        asm volatile("{\n\t.reg .pred P1;\n\t"
                     "W_%=:\n\t"
                     "mbarrier.try_wait.parity.acquire.cta.shared::cta.b64 P1, [%0], %1, 0x989680;\n\t"
                     "@P1 bra.uni D_%=;\n\t"
                     "bra.uni W_%=;\n\t"
                     "D_%=:\n\t}"
                     :: "r"(mbar), "r"(parity) : "memory");
    }
}

#define TCGEN05_ALLOC(sm_addr, nc) \
    asm volatile("tcgen05.alloc.cta_group::1.sync.aligned.shared::cta.b32 [%0], %1;" \
                 :: "r"((uint32_t)(sm_addr)), "r"((uint32_t)(nc)) : "memory")
#define TCGEN05_DEALLOC(tmem, nc) \
    asm volatile("tcgen05.dealloc.cta_group::1.sync.aligned.b32 %0, %1;" :: "r"(tmem), "r"(nc))
#define TCGEN05_COMMIT_MC(mbar, mask) \
    asm volatile("tcgen05.commit.cta_group::1.mbarrier::arrive::one.shared::cluster.multicast::cluster.b64 [%0], %1;" \
                 :: "r"((uint32_t)(mbar)), "h"((uint16_t)(mask)) : "memory")
#define TCGEN05_FENCE_AFTER()  asm volatile("tcgen05.fence::after_thread_sync;" ::: "memory")
#define TCGEN05_FENCE_BEFORE() asm volatile("tcgen05.fence::before_thread_sync;" ::: "memory")
#define TCGEN05_WAIT_LD()      asm volatile("tcgen05.wait::ld.sync.aligned;" ::: "memory")

#define TCGEN05_LD_X32(r, ta) \
    asm volatile("tcgen05.ld.sync.aligned.32x32b.x32.b32 " \
        "{%0, %1, %2, %3, %4, %5, %6, %7, %8, %9, %10, %11, %12, %13, %14, %15, " \
        " %16, %17, %18, %19, %20, %21, %22, %23, %24, %25, %26, %27, %28, %29, %30, %31}, [%32];" \
        : "=r"((r)[0]),  "=r"((r)[1]),  "=r"((r)[2]),  "=r"((r)[3]), \
          "=r"((r)[4]),  "=r"((r)[5]),  "=r"((r)[6]),  "=r"((r)[7]), \
          "=r"((r)[8]),  "=r"((r)[9]),  "=r"((r)[10]), "=r"((r)[11]), \
          "=r"((r)[12]), "=r"((r)[13]), "=r"((r)[14]), "=r"((r)[15]), \
          "=r"((r)[16]), "=r"((r)[17]), "=r"((r)[18]), "=r"((r)[19]), \
          "=r"((r)[20]), "=r"((r)[21]), "=r"((r)[22]), "=r"((r)[23]), \
          "=r"((r)[24]), "=r"((r)[25]), "=r"((r)[26]), "=r"((r)[27]), \
          "=r"((r)[28]), "=r"((r)[29]), "=r"((r)[30]), "=r"((r)[31]) \
        : "r"(ta))

static constexpr uint64_t DESC_BASE =
    (uint64_t(2) << 61) | (uint64_t(1) << 46) | (uint64_t(64) << 32) | (uint64_t(1) << 16);
DEV_INLINE uint64_t make_desc(uint32_t addr) {
    return DESC_BASE | ((uint64_t)(addr >> 4) & 0x3FFF);
}
// idesc kind::f16: fp32 acc, bf16 A, bf16 B, M=128, N=128
#define MMA_IDESC ((1u << 4) | (1u << 7) | (1u << 10) | ((128u / 8u) << 17) | ((128u / 16u) << 24))

DEV_INLINE void mma_bf16_ss(uint32_t d_tmem, uint64_t a_desc, uint64_t b_desc, uint32_t en) {
    asm volatile("{\n\t.reg .pred p;\n\tsetp.ne.u32 p, %4, 0;\n\t"
                 "tcgen05.mma.cta_group::1.kind::f16 [%0], %1, %2, %3, {%5, %5, %5, %5}, p;\n\t}"
                 :: "r"(d_tmem), "l"(a_desc), "l"(b_desc), "r"(MMA_IDESC),
                    "r"(en), "r"(0u)
                 : "memory");
}

// 2D TMA load, CTA-local
DEV_INLINE void tma2d(uint32_t dst, const CUtensorMap* map, int x, int y, uint32_t mbar) {
    asm volatile("cp.async.bulk.tensor.2d.shared::cta.global.tile.mbarrier::complete_tx::bytes "
                 "[%0], [%1, {%2, %3}], [%4];"
                 :: "r"(dst), "l"(map), "r"(x), "r"(y), "r"(mbar) : "memory");
}
// 2D TMA load, multicast to every CTA in mask (same smem offset + complete_tx each)
DEV_INLINE void tma2d_mc(uint32_t dst, const CUtensorMap* map, int x, int y,
                         uint32_t mbar, uint16_t mask) {
    asm volatile("cp.async.bulk.tensor.2d.shared::cluster.global.tile"
                 ".mbarrier::complete_tx::bytes.multicast::cluster "
                 "[%0], [%1, {%2, %3}], [%4], %5;"
                 :: "r"(dst), "l"(map), "r"(x), "r"(y), "r"(mbar), "h"(mask) : "memory");
}
#endif // USE_TC

// ---------------- split helpers ----------------
DEV_INLINE void split1(float v, __nv_bfloat16& h, __nv_bfloat16& l) {
    h = __float2bfloat16(v);
    l = __float2bfloat16(v - __bfloat162float(h));
}

// ---------------- prep kernel 1: split x into bf16 hi/lo ----------------
__global__ void split_x_kernel(const float* __restrict__ x) {
    long i = ((long)blockIdx.x * blockDim.x + threadIdx.x) * 4;
    float4 v = *(const float4*)(x + i);
    __nv_bfloat16 h0, h1, h2, h3, l0, l1, l2, l3;
    split1(v.x, h0, l0); split1(v.y, h1, l1); split1(v.z, h2, l2); split1(v.w, h3, l3);
    ushort4 hv, lv;
    hv.x = __bfloat16_as_ushort(h0); hv.y = __bfloat16_as_ushort(h1);
    hv.z = __bfloat16_as_ushort(h2); hv.w = __bfloat16_as_ushort(h3);
    lv.x = __bfloat16_as_ushort(l0); lv.y = __bfloat16_as_ushort(l1);
    lv.z = __bfloat16_as_ushort(l2); lv.w = __bfloat16_as_ushort(l3);
    *(ushort4*)((unsigned short*)g_xh + i) = hv;
    *(ushort4*)((unsigned short*)g_xl + i) = lv;
}

// ---------------- prep kernel 2: transpose-split W -> wh/wl [j][k] ----------------
__global__ void split_w_kernel(const float* __restrict__ W) {   // W[k][j] row-major
    __shared__ float t[32][33];
    int j0 = blockIdx.x * 32, k0 = blockIdx.y * 32;
    int tx = threadIdx.x, ty = threadIdx.y;   // block (32, 8)
#pragma unroll
    for (int r = ty; r < 32; r += 8)
        t[r][tx] = W[(long)(k0 + r) * M_DIM + j0 + tx];
    __syncthreads();
#pragma unroll
    for (int r = ty; r < 32; r += 8) {
        float v = t[tx][r];                   // = W[k0+tx][j0+r]
        __nv_bfloat16 h, l; split1(v, h, l);
        long o = (long)(j0 + r) * K_DIM + k0 + tx;
        g_wh[o] = h; g_wl[o] = l;
    }
}

// ---------------- prep kernel 3: probs + bias fold ----------------
// probs[j] = (1/K_DIM) * prod_{d<9,g<3} cos^2(E[d, j, g])   (state stays row-constant)
__global__ void probs_kernel(const float* __restrict__ E, const float* __restrict__ cb) {
    int j = blockIdx.x * blockDim.x + threadIdx.x;
    if (j >= M_DIM) return;
    float p = 1.0f;
#pragma unroll
    for (int d = 0; d < 9; d++) {
#pragma unroll
        for (int g = 0; g < 3; g++) {
            float a = E[(long)d * K_DIM * M_DIM + (long)j * M_DIM + g];
            float c = cosf(a);
            p *= c * c;
        }
    }
    g_bias[j] = cb[j] + p * (1.0f / (float)K_DIM);
}

#if !USE_TC
// ---------------- hmma tile loader (fallback pass only) ----------------
DEV_INLINE void load_tile_mm(uint32_t smem_base, int stage, int kt, int tileM, int tileN, int tid) {
    uint32_t sb = smem_base + TILE_BASE + stage * MM_STAGE;
#pragma unroll
    for (int i = tid; i < 3072; i += THREADS) {
        if (i < 1024) {
            int hl = i >> 9;
            int t = i & 511; int r = t >> 2, c = t & 3;
            uint32_t dst = sb + hl * MM_A_BYTES + r * MM_ROWB + c * 16;
            long src = (long)(tileM * BM + r) * (K_DIM * 2) + (long)kt * (MM_BK * 2) + c * 16;
            cp16(dst, (const char*)(hl ? (const void*)g_xl : (const void*)g_xh) + src);
        } else {
            int j = i - 1024; int hl = j >> 10;
            int t = j & 1023; int r = t >> 2, c = t & 3;
            uint32_t dst = sb + 2 * MM_A_BYTES + hl * MM_B_BYTES + r * MM_ROWB + c * 16;
            long src = (long)(tileN * BN + r) * (K_DIM * 2) + (long)kt * (MM_BK * 2) + c * 16;
            cp16(dst, (const char*)(hl ? (const void*)g_wl : (const void*)g_wh) + src);
        }
    }
    cp_commit();
}
#endif

// ---------------- main GEMM: warp-specialized TMA + tcgen05, fused tanh epilogue ----------------
__global__ void __launch_bounds__(THREADS, 1) __cluster_dims__(CLUSTER_SZ, 1, 1)
gemm_kernel(float* __restrict__ out,
            const __grid_constant__ CUtensorMap mAh,
            const __grid_constant__ CUtensorMap mAl,
            const __grid_constant__ CUtensorMap mBh,
            const __grid_constant__ CUtensorMap mBl) {
    extern __shared__ char smem[];
    uint32_t smem_base = smem_u32(smem);
    int tid = threadIdx.x;
    int wid = tid >> 5, lid = tid & 31;
    int bid = blockIdx.x;
    int tileM = bid & 31;   // pair (2k, 2k+1): consecutive tileM, same tileN -> share B
    int tileN = bid >> 5;   // 0..7

#if USE_TC
    // ================= tcgen05 + TMA multicast path =================
    uint32_t rank = ctarank();

    if (wid == 0) TCGEN05_ALLOC(smem_base + SMEM_TMEM_PTR, 256);
    if (tid == 0) {
        MBAR_INIT(smem_base + SMEM_FULL0, 1);   // arrive: producer expect_tx
        MBAR_INIT(smem_base + SMEM_FULL1, 1);
        MBAR_INIT(smem_base + SMEM_DONE0, 2);   // arrive: commit-mc from both CTAs
        MBAR_INIT(smem_base + SMEM_DONE1, 2);
        MBAR_INIT(smem_base + SMEM_FINAL, 2);
    }
    __syncthreads();
    uint32_t tmem;
    asm volatile("ld.shared.b32 %0, [%1];" : "=r"(tmem) : "r"(smem_base + SMEM_TMEM_PTR));

    // Both CTAs' barriers must be live before any multicast TMA targets them.
    CLUSTER_SYNC();

    uint32_t epred = elect_one();

    if (wid == 1 && epred) {
        // ---- producer: 4 TMA per stage, paced by cluster-wide MMA completion ----
        uint32_t pd0 = 0, pd1 = 0;
        int arow = tileM * BM;
        int brow = tileN * BN + (int)rank * 128;
        for (int kt = 0; kt < TC_NT; ++kt) {
            int s = kt & 1;
            uint32_t fb = smem_base + (s ? SMEM_FULL1 : SMEM_FULL0);
            if (kt >= 2) {
                uint32_t db = smem_base + (s ? SMEM_DONE1 : SMEM_DONE0);
                if (s) { mbar_wait(db, pd1); pd1 ^= 1; }
                else   { mbar_wait(db, pd0); pd0 ^= 1; }
            }
            MBAR_EXPECT_TX(fb, STAGE_BYTES);
            uint32_t sa = smem_base + TILE_BASE + s * STAGE_BYTES;
            int kx = kt * TC_BK;
            tma2d(sa,           &mAh, kx, arow, fb);
            tma2d(sa + A_BYTES, &mAl, kx, arow, fb);
            // B halves: each rank loads its 128 rows and multicasts to both CTAs
            tma2d_mc(sa + 2 * A_BYTES           + rank * 16384, &mBh, kx, brow, fb, 3);
            tma2d_mc(sa + 2 * A_BYTES + B_BYTES + rank * 16384, &mBl, kx, brow, fb, 3);
        }
    } else if (wid == 0 && epred) {
        // ---- consumer: 24 MMAs per stage, commit -> done (both CTAs) ----
        uint32_t pf0 = 0, pf1 = 0;
        for (int kt = 0; kt < TC_NT; ++kt) {
            int s = kt & 1;
            uint32_t fb = smem_base + (s ? SMEM_FULL1 : SMEM_FULL0);
            if (s) { mbar_wait(fb, pf1); pf1 ^= 1; }
            else   { mbar_wait(fb, pf0); pf0 ^= 1; }

            uint32_t sa  = smem_base + TILE_BASE + s * STAGE_BYTES;
            uint64_t dah = make_desc(sa);
            uint64_t dal = make_desc(sa + A_BYTES);
            uint64_t dbh = make_desc(sa + 2 * A_BYTES);
            uint64_t dbl = make_desc(sa + 2 * A_BYTES + B_BYTES);
#pragma unroll
            for (int ks = 0; ks < 4; ++ks) {               // K=16 per MMA
                uint64_t o = (uint64_t)(ks * 2);
#pragma unroll
                for (int h = 0; h < 2; ++h) {              // two N=128 halves
                    uint64_t bo = o + (uint64_t)h * 1024;  // 128 rows * 128B = 1024 units
                    uint32_t dd = tmem + h * 128;
                    uint32_t acc = (kt > 0) || (ks > 0);
                    mma_bf16_ss(dd, dah + o, dbh + bo, acc);  // hi*hi
                    mma_bf16_ss(dd, dah + o, dbl + bo, 1u);   // hi*lo
                    mma_bf16_ss(dd, dal + o, dbh + bo, 1u);   // lo*hi
                }
            }
            TCGEN05_COMMIT_MC(smem_base + (s ? SMEM_DONE1 : SMEM_DONE0), 3);
        }
        TCGEN05_COMMIT_MC(smem_base + SMEM_FINAL, 3);      // tracks ALL prior MMAs
    }

    // Everyone: wait for all MMAs in BOTH cluster CTAs (count=2, first phase).
    mbar_wait(smem_base + SMEM_FINAL, 0);
    TCGEN05_FENCE_AFTER();

    // Epilogue: 16 warps. warp w -> TMEM lanes (w%4)*32 (its subpartition), cols (w/4)*64
    {
        int rrow  = (wid & 3) * 32 + lid;
        long gm   = (long)tileM * BM + rrow;
        int cbase = (wid >> 2) * 64;
#pragma unroll
        for (int cc = 0; cc < 2; ++cc) {
            uint32_t d[32];
            TCGEN05_LD_X32(d, tmem + cbase + cc * 32);
            TCGEN05_WAIT_LD();
            int gc = tileN * BN + cbase + cc * 32;
            const float4* bp = (const float4*)(g_bias + gc);
            float4* op = (float4*)(out + gm * M_DIM + gc);
#pragma unroll
            for (int q = 0; q < 8; ++q) {
                float4 b = bp[q];
                float4 o;
                o.x = tanhf(__uint_as_float(d[q * 4 + 0]) + b.x);
                o.y = tanhf(__uint_as_float(d[q * 4 + 1]) + b.y);
                o.z = tanhf(__uint_as_float(d[q * 4 + 2]) + b.z);
                o.w = tanhf(__uint_as_float(d[q * 4 + 3]) + b.w);
                op[q] = o;
            }
        }
        TCGEN05_FENCE_BEFORE();
    }

    __syncthreads();
    if (tid == 0) {
        MBAR_INVAL(smem_base + SMEM_FULL0); MBAR_INVAL(smem_base + SMEM_FULL1);
        MBAR_INVAL(smem_base + SMEM_DONE0); MBAR_INVAL(smem_base + SMEM_DONE1);
        MBAR_INVAL(smem_base + SMEM_FINAL);
    }
    __syncthreads();
    if (wid == 0) TCGEN05_DEALLOC(tmem, 256);
    // No CTA exits while a peer's multicast targeting this CTA could be in flight.
    CLUSTER_SYNC();

#else
    // ================= HMMA fallback (base-PTX legal; never runs on GB300) =================
    int wr = wid & 3;
    int wc = wid >> 2;

    float acc[2][8][4];
#pragma unroll
    for (int mt = 0; mt < 2; ++mt)
#pragma unroll
        for (int nt = 0; nt < 8; ++nt)
#pragma unroll
            for (int q = 0; q < 4; ++q) acc[mt][nt][q] = 0.0f;

    load_tile_mm(smem_base, 0, 0, tileM, tileN, tid);
    load_tile_mm(smem_base, 1, 1, tileM, tileN, tid);
    load_tile_mm(smem_base, 2, 2, tileM, tileN, tid);

    const int lrow = lid & 15;
    const int lk16b = (lid >> 4) * 16;

    for (int kt = 0; kt < MM_NT; ++kt) {
        asm volatile("cp.async.wait_group 2;" ::: "memory");
        __syncthreads();

        int s = kt % MM_STAGES;
        uint32_t sb  = smem_base + TILE_BASE + s * MM_STAGE;
        uint32_t sAh = sb;
        uint32_t sAl = sb + MM_A_BYTES;
        uint32_t sBh = sb + 2 * MM_A_BYTES;
        uint32_t sBl = sb + 2 * MM_A_BYTES + MM_B_BYTES;

#pragma unroll
        for (int k16 = 0; k16 < 2; ++k16) {
            uint32_t koff = k16 * 32 + lk16b;
            uint32_t aoff = (uint32_t)(wr * 32 + lrow) * MM_ROWB + koff;
            uint32_t boff = (uint32_t)(wc * 64 + lrow) * MM_ROWB + koff;

            uint32_t ah[2][4], bh[4][4];
            ldsm4(ah[0], sAh + aoff);
            ldsm4(ah[1], sAh + aoff + 16 * MM_ROWB);
#pragma unroll
            for (int g = 0; g < 4; ++g) ldsm4(bh[g], sBh + boff + g * 16 * MM_ROWB);

#pragma unroll
            for (int mt = 0; mt < 2; ++mt)
#pragma unroll
                for (int nt = 0; nt < 8; ++nt)
                    mma16816(acc[mt][nt], ah[mt], bh[nt >> 1][nt & 1], bh[nt >> 1][(nt & 1) + 2]);

            uint32_t al[2][4];
            ldsm4(al[0], sAl + aoff);
            ldsm4(al[1], sAl + aoff + 16 * MM_ROWB);
#pragma unroll
            for (int mt = 0; mt < 2; ++mt)
#pragma unroll
                for (int nt = 0; nt < 8; ++nt)
                    mma16816(acc[mt][nt], al[mt], bh[nt >> 1][nt & 1], bh[nt >> 1][(nt & 1) + 2]);

            uint32_t bl[4][4];
#pragma unroll
            for (int g = 0; g < 4; ++g) ldsm4(bl[g], sBl + boff + g * 16 * MM_ROWB);
#pragma unroll
            for (int mt = 0; mt < 2; ++mt)
#pragma unroll
                for (int nt = 0; nt < 8; ++nt)
                    mma16816(acc[mt][nt], ah[mt], bl[nt >> 1][nt & 1], bl[nt >> 1][(nt & 1) + 2]);
        }

        __syncthreads();
        if (kt + MM_STAGES < MM_NT)
            load_tile_mm(smem_base, s, kt + MM_STAGES, tileM, tileN, tid);
    }

    {
        int r0 = tileM * BM + wr * 32 + (lid >> 2);
        int c0 = tileN * BN + wc * 64 + (lid & 3) * 2;
#pragma unroll
        for (int mt = 0; mt < 2; ++mt) {
#pragma unroll
            for (int nt = 0; nt < 8; ++nt) {
                int row = r0 + mt * 16;
                int col = c0 + nt * 8;
                float2 bv = *(const float2*)(g_bias + col);
                float2 o0, o1;
                o0.x = tanhf(acc[mt][nt][0] + bv.x);
                o0.y = tanhf(acc[mt][nt][1] + bv.y);
                o1.x = tanhf(acc[mt][nt][2] + bv.x);
                o1.y = tanhf(acc[mt][nt][3] + bv.y);
                *(float2*)(out + (long)row * M_DIM + col) = o0;
                *(float2*)(out + (long)(row + 8) * M_DIM + col) = o1;
            }
        }
    }
#endif
}

// ---------------- host: tensormap creation via driver entry point ----------------
typedef CUresult (*EncodeTiledFn)(
    CUtensorMap*, CUtensorMapDataType, cuuint32_t, void*,
    const cuuint64_t*, const cuuint64_t*, const cuuint32_t*, const cuuint32_t*,
    CUtensorMapInterleave, CUtensorMapSwizzle, CUtensorMapL2promotion, CUtensorMapFloatOOBfill);

static void make_map(EncodeTiledFn enc, CUtensorMap* m, void* base, unsigned long long rows) {
    cuuint64_t dims[2]    = {(cuuint64_t)K_DIM, (cuuint64_t)rows};
    cuuint64_t strides[1] = {(cuuint64_t)K_DIM * 2};           // bytes between rows
    cuuint32_t box[2]     = {64, 128};                         // 128B x 128 rows (SW128)
    cuuint32_t es[2]      = {1, 1};
    enc(m, CU_TENSOR_MAP_DATA_TYPE_BFLOAT16, 2, base, dims, strides, box, es,
        CU_TENSOR_MAP_INTERLEAVE_NONE, CU_TENSOR_MAP_SWIZZLE_128B,
        CU_TENSOR_MAP_L2_PROMOTION_L2_128B, CU_TENSOR_MAP_FLOAT_OOB_FILL_NONE);
}

extern "C" void kernel_launch(void* const* d_in, const int* in_sizes, int n_in,
                              void* d_out, int out_size) {
    const float* x  = (const float*)d_in[0];
    const float* E  = (const float*)d_in[1];
    // d_in[2] = eternal_biases: unused by the reference as well
    const float* W  = (const float*)d_in[3];
    const float* cb = (const float*)d_in[4];
    float* out = (float*)d_out;

    // tensormaps (host-side; recreated per call — deterministic, no device work)
    EncodeTiledFn enc = nullptr;
    cudaDriverEntryPointQueryResult qr;
    cudaGetDriverEntryPointByVersion("cuTensorMapEncodeTiled", (void**)&enc, 12000,
                                     cudaEnableDefault, &qr);
    void *pxh, *pxl, *pwh, *pwl;
    cudaGetSymbolAddress(&pxh, g_xh);
    cudaGetSymbolAddress(&pxl, g_xl);
    cudaGetSymbolAddress(&pwh, g_wh);
    cudaGetSymbolAddress(&pwl, g_wl);
    CUtensorMap mAh, mAl, mBh, mBl;
    make_map(enc, &mAh, pxh, B_DIM);
    make_map(enc, &mAl, pxl, B_DIM);
    make_map(enc, &mBh, pwh, M_DIM);
    make_map(enc, &mBl, pwl, M_DIM);

    cudaFuncSetAttribute(gemm_kernel, cudaFuncAttributeMaxDynamicSharedMemorySize, SMEM_TOTAL);

    split_x_kernel<<<(int)(((long)B_DIM * K_DIM / 4) / 256), 256>>>(x);
    split_w_kernel<<<dim3(M_DIM / 32, K_DIM / 32), dim3(32, 8)>>>(W);
    probs_kernel<<<M_DIM / 256, 256>>>(E, cb);
    gemm_kernel<<<(B_DIM / BM) * (M_DIM / BN), THREADS, SMEM_TOTAL>>>(out, mAh, mAl, mBh, mBl);
}

// round 8
// speedup vs baseline: 1.3571x; 1.1003x over previous
#include <cuda_runtime.h>
#include <cuda.h>
#include <cuda_bf16.h>
#include <cstdint>
#include <math.h>

#define DEV_INLINE __device__ __forceinline__

// Does this compilation pass target sm_103a (arch-specific features available)?
#ifdef __CUDA_ARCH_FEAT_SM103_ALL
#define USE_TC 1
#else
#define USE_TC 0
#endif

// ---------------- problem constants ----------------
#define B_DIM 4096          // batch rows (GEMM M)
#define K_DIM 2048          // inner dim  (GEMM K)
#define M_DIM 2048          // out cols   (GEMM N)

// ---------------- GEMM tiling (both paths: CTA covers 128 x 256) ----------------
#define BM 128
#define BN 256
#define THREADS 512
#define CLUSTER_SZ 2

// ---- tcgen05 path smem: 4-stage ring, BK=32 (SW64, 64B rows) ----
#define SMEM_TMEM_PTR 0
#define SMEM_FULL(s)  (8 + (s) * 8)            // 4 full barriers
#define SMEM_DONE(s)  (40 + (s) * 8)           // 4 done barriers
#define SMEM_FINAL    72
#define TILE_BASE     1024
#define TC_BK         32
#define TC_NT         (K_DIM / TC_BK)          // 64
#define NSTAGE        4
#define STG_A         0                        // Ah (8KB)
#define STG_AL        8192                     // Al (8KB)
#define STG_BH        16384                    // Bh (two 8KB rank halves)
#define STG_BL        32768                    // Bl (two 8KB rank halves)
#define STAGE_BYTES   49152                    // 48KB
#define SMEM_TOTAL    (TILE_BASE + NSTAGE * STAGE_BYTES)   // 197632

// ---- hmma fallback smem (compile-legality for the compute_103 PTX pass) ----
#define MM_BK         32
#define MM_NT         (K_DIM / MM_BK)              // 64
#define MM_ROWB       80                           // 64B row + 16B pad
#define MM_A_BYTES    (BM * MM_ROWB)               // 10240
#define MM_B_BYTES    (BN * MM_ROWB)               // 20480
#define MM_STAGE      (2 * MM_A_BYTES + 2 * MM_B_BYTES)  // 61440
#define MM_STAGES     3

// ---------------- device scratch (allocation-free rule: __device__ globals) ----------------
__device__ __align__(16) __nv_bfloat16 g_xh[(long)B_DIM * K_DIM];
__device__ __align__(16) __nv_bfloat16 g_xl[(long)B_DIM * K_DIM];
__device__ __align__(16) __nv_bfloat16 g_wh[(long)M_DIM * K_DIM];   // [j][k] (transposed W)
__device__ __align__(16) __nv_bfloat16 g_wl[(long)M_DIM * K_DIM];
__device__ float g_bias[M_DIM];                                     // classical_bias + probs

// ---------------- PTX helpers (base-arch legal) ----------------
DEV_INLINE uint32_t smem_u32(const void* p) {
    uint32_t a;
    asm("{ .reg .u64 t; cvta.to.shared.u64 t, %1; cvt.u32.u64 %0, t; }" : "=r"(a) : "l"(p));
    return a;
}

DEV_INLINE void cp16(uint32_t dst, const void* src) {
    asm volatile("cp.async.cg.shared.global [%0], [%1], 16;" :: "r"(dst), "l"(src) : "memory");
}
DEV_INLINE void cp_commit() { asm volatile("cp.async.commit_group;" ::: "memory"); }

DEV_INLINE void ldsm4(uint32_t* r, uint32_t addr) {
    asm volatile("ldmatrix.sync.aligned.m8n8.x4.shared.b16 {%0,%1,%2,%3}, [%4];"
                 : "=r"(r[0]), "=r"(r[1]), "=r"(r[2]), "=r"(r[3]) : "r"(addr));
}
DEV_INLINE void mma16816(float* c, const uint32_t* a, uint32_t b0, uint32_t b1) {
    asm volatile("mma.sync.aligned.m16n8k16.row.col.f32.bf16.bf16.f32 "
                 "{%0,%1,%2,%3}, {%4,%5,%6,%7}, {%8,%9}, {%0,%1,%2,%3};"
                 : "+f"(c[0]), "+f"(c[1]), "+f"(c[2]), "+f"(c[3])
                 : "r"(a[0]), "r"(a[1]), "r"(a[2]), "r"(a[3]), "r"(b0), "r"(b1));
}

#if USE_TC
// ---------------- tcgen05 / TMA helpers (only in the sm_103a pass) ----------------
DEV_INLINE uint32_t elect_one() {
    uint32_t pred;
    asm volatile("{\n\t.reg .pred p;\n\telect.sync _|p, 0xFFFFFFFF;\n\t"
                 "selp.b32 %0, 1, 0, p;\n\t}" : "=r"(pred));
    return pred;
}
DEV_INLINE uint32_t ctarank() {
    uint32_t r;
    asm("mov.u32 %0, %%cluster_ctarank;" : "=r"(r));
    return r;
}
#define MBAR_INIT(addr, cnt) \
    asm volatile("mbarrier.init.shared.b64 [%0], %1;" :: "r"(addr), "r"(cnt) : "memory")
#define MBAR_INVAL(addr) \
    asm volatile("mbarrier.inval.shared.b64 [%0];" :: "r"(addr) : "memory")
#define MBAR_EXPECT_TX(addr, tx) \
    asm volatile("mbarrier.arrive.expect_tx.shared.b64 _, [%0], %1;" \
                 :: "r"(addr), "r"((uint32_t)(tx)) : "memory")
#define CLUSTER_SYNC() do { \
    asm volatile("barrier.cluster.arrive.aligned;" ::: "memory"); \
    asm volatile("barrier.cluster.wait.aligned;" ::: "memory"); \
} while (0)

DEV_INLINE void mbar_wait(uint32_t mbar, uint32_t parity) {
    uint32_t done;
    asm volatile("{\n\t.reg .pred p;\n\t"
                 "mbarrier.try_wait.parity.acquire.cta.shared::cta.b64 p, [%1], %2;\n\t"
                 "selp.b32 %0, 1, 0, p;\n\t}"
                 : "=r"(done) : "r"(mbar), "r"(parity) : "memory");
    if (!done) {
        asm volatile("{\n\t.reg .pred P1;\n\t"
                     "W_%=:\n\t"
                     "mbarrier.try_wait.parity.acquire.cta.shared::cta.b64 P1, [%0], %1, 0x989680;\n\t"
                     "@P1 bra.uni D_%=;\n\t"
                     "bra.uni W_%=;\n\t"
                     "D_%=:\n\t}"
                     :: "r"(mbar), "r"(parity) : "memory");
    }
}

#define TCGEN05_ALLOC(sm_addr, nc) \
    asm volatile("tcgen05.alloc.cta_group::1.sync.aligned.shared::cta.b32 [%0], %1;" \
                 :: "r"((uint32_t)(sm_addr)), "r"((uint32_t)(nc)) : "memory")
#define TCGEN05_DEALLOC(tmem, nc) \
    asm volatile("tcgen05.dealloc.cta_group::1.sync.aligned.b32 %0, %1;" :: "r"(tmem), "r"(nc))
#define TCGEN05_COMMIT_MC(mbar, mask) \
    asm volatile("tcgen05.commit.cta_group::1.mbarrier::arrive::one.shared::cluster.multicast::cluster.b64 [%0], %1;" \
                 :: "r"((uint32_t)(mbar)), "h"((uint16_t)(mask)) : "memory")
#define TCGEN05_FENCE_AFTER()  asm volatile("tcgen05.fence::after_thread_sync;" ::: "memory")
#define TCGEN05_FENCE_BEFORE() asm volatile("tcgen05.fence::before_thread_sync;" ::: "memory")
#define TCGEN05_WAIT_LD()      asm volatile("tcgen05.wait::ld.sync.aligned;" ::: "memory")

#define TCGEN05_LD_X32(r, ta) \
    asm volatile("tcgen05.ld.sync.aligned.32x32b.x32.b32 " \
        "{%0, %1, %2, %3, %4, %5, %6, %7, %8, %9, %10, %11, %12, %13, %14, %15, " \
        " %16, %17, %18, %19, %20, %21, %22, %23, %24, %25, %26, %27, %28, %29, %30, %31}, [%32];" \
        : "=r"((r)[0]),  "=r"((r)[1]),  "=r"((r)[2]),  "=r"((r)[3]), \
          "=r"((r)[4]),  "=r"((r)[5]),  "=r"((r)[6]),  "=r"((r)[7]), \
          "=r"((r)[8]),  "=r"((r)[9]),  "=r"((r)[10]), "=r"((r)[11]), \
          "=r"((r)[12]), "=r"((r)[13]), "=r"((r)[14]), "=r"((r)[15]), \
          "=r"((r)[16]), "=r"((r)[17]), "=r"((r)[18]), "=r"((r)[19]), \
          "=r"((r)[20]), "=r"((r)[21]), "=r"((r)[22]), "=r"((r)[23]), \
          "=r"((r)[24]), "=r"((r)[25]), "=r"((r)[26]), "=r"((r)[27]), \
          "=r"((r)[28]), "=r"((r)[29]), "=r"((r)[30]), "=r"((r)[31]) \
        : "r"(ta))

// SW64 K-major descriptor: layout=4, version=1, SBO=32 (8 rows x 64B = 512B), LBO=1
static constexpr uint64_t DESC_BASE_SW64 =
    (uint64_t(4) << 61) | (uint64_t(1) << 46) | (uint64_t(32) << 32) | (uint64_t(1) << 16);
DEV_INLINE uint64_t make_desc64(uint32_t addr) {
    return DESC_BASE_SW64 | ((uint64_t)(addr >> 4) & 0x3FFF);
}
// idesc kind::f16: fp32 acc, bf16 A, bf16 B, M=128, N=128
#define MMA_IDESC ((1u << 4) | (1u << 7) | (1u << 10) | ((128u / 8u) << 17) | ((128u / 16u) << 24))

DEV_INLINE void mma_bf16_ss(uint32_t d_tmem, uint64_t a_desc, uint64_t b_desc, uint32_t en) {
    asm volatile("{\n\t.reg .pred p;\n\tsetp.ne.u32 p, %4, 0;\n\t"
                 "tcgen05.mma.cta_group::1.kind::f16 [%0], %1, %2, %3, {%5, %5, %5, %5}, p;\n\t}"
                 :: "r"(d_tmem), "l"(a_desc), "l"(b_desc), "r"(MMA_IDESC),
                    "r"(en), "r"(0u)
                 : "memory");
}

// 2D TMA load, CTA-local
DEV_INLINE void tma2d(uint32_t dst, const CUtensorMap* map, int x, int y, uint32_t mbar) {
    asm volatile("cp.async.bulk.tensor.2d.shared::cta.global.tile.mbarrier::complete_tx::bytes "
                 "[%0], [%1, {%2, %3}], [%4];"
                 :: "r"(dst), "l"(map), "r"(x), "r"(y), "r"(mbar) : "memory");
}
// 2D TMA load, multicast to every CTA in mask
DEV_INLINE void tma2d_mc(uint32_t dst, const CUtensorMap* map, int x, int y,
                         uint32_t mbar, uint16_t mask) {
    asm volatile("cp.async.bulk.tensor.2d.shared::cluster.global.tile"
                 ".mbarrier::complete_tx::bytes.multicast::cluster "
                 "[%0], [%1, {%2, %3}], [%4], %5;"
                 :: "r"(dst), "l"(map), "r"(x), "r"(y), "r"(mbar), "h"(mask) : "memory");
}
#endif // USE_TC

// ---------------- split helpers ----------------
DEV_INLINE void split1(float v, __nv_bfloat16& h, __nv_bfloat16& l) {
    h = __float2bfloat16(v);
    l = __float2bfloat16(v - __bfloat162float(h));
}

// ---------------- fused prep kernel: split_x + transpose-split_w + probs ----------------
#define PREP_X_BLOCKS 8192     // 8M elems, 4/thread, 256 thr
#define PREP_W_BLOCKS 4096     // 64 x 64 tiles of 32x32
#define PREP_P_BLOCKS 8        // 2048 cols / 256
__global__ void prep_kernel(const float* __restrict__ x, const float* __restrict__ W,
                            const float* __restrict__ E, const float* __restrict__ cb) {
    int b = blockIdx.x;
    int tid = threadIdx.x;
    if (b < PREP_X_BLOCKS) {
        // ---- split x ----
        long i = ((long)b * 256 + tid) * 4;
        float4 v = *(const float4*)(x + i);
        __nv_bfloat16 h0, h1, h2, h3, l0, l1, l2, l3;
        split1(v.x, h0, l0); split1(v.y, h1, l1); split1(v.z, h2, l2); split1(v.w, h3, l3);
        ushort4 hv, lv;
        hv.x = __bfloat16_as_ushort(h0); hv.y = __bfloat16_as_ushort(h1);
        hv.z = __bfloat16_as_ushort(h2); hv.w = __bfloat16_as_ushort(h3);
        lv.x = __bfloat16_as_ushort(l0); lv.y = __bfloat16_as_ushort(l1);
        lv.z = __bfloat16_as_ushort(l2); lv.w = __bfloat16_as_ushort(l3);
        *(ushort4*)((unsigned short*)g_xh + i) = hv;
        *(ushort4*)((unsigned short*)g_xl + i) = lv;
    } else if (b < PREP_X_BLOCKS + PREP_W_BLOCKS) {
        // ---- transpose-split W ----
        __shared__ float t[32][33];
        int wb = b - PREP_X_BLOCKS;
        int j0 = (wb & 63) * 32, k0 = (wb >> 6) * 32;
        int tx = tid & 31, ty = tid >> 5;     // 32 x 8
#pragma unroll
        for (int r = ty; r < 32; r += 8)
            t[r][tx] = W[(long)(k0 + r) * M_DIM + j0 + tx];
        __syncthreads();
#pragma unroll
        for (int r = ty; r < 32; r += 8) {
            float v = t[tx][r];               // = W[k0+tx][j0+r]
            __nv_bfloat16 h, l; split1(v, h, l);
            long o = (long)(j0 + r) * K_DIM + k0 + tx;
            g_wh[o] = h; g_wl[o] = l;
        }
    } else {
        // ---- probs + bias fold: probs[j] = (1/K) * prod cos^2(E[d,j,g]) ----
        int j = (b - PREP_X_BLOCKS - PREP_W_BLOCKS) * 256 + tid;
        if (j < M_DIM) {
            float p = 1.0f;
#pragma unroll
            for (int d = 0; d < 9; d++)
#pragma unroll
                for (int g = 0; g < 3; g++) {
                    float a = E[(long)d * K_DIM * M_DIM + (long)j * M_DIM + g];
                    float c = cosf(a);
                    p *= c * c;
                }
            g_bias[j] = cb[j] + p * (1.0f / (float)K_DIM);
        }
    }
}

#if !USE_TC
// ---------------- hmma tile loader (fallback pass only) ----------------
DEV_INLINE void load_tile_mm(uint32_t smem_base, int stage, int kt, int tileM, int tileN, int tid) {
    uint32_t sb = smem_base + TILE_BASE + stage * MM_STAGE;
#pragma unroll
    for (int i = tid; i < 3072; i += THREADS) {
        if (i < 1024) {
            int hl = i >> 9;
            int t = i & 511; int r = t >> 2, c = t & 3;
            uint32_t dst = sb + hl * MM_A_BYTES + r * MM_ROWB + c * 16;
            long src = (long)(tileM * BM + r) * (K_DIM * 2) + (long)kt * (MM_BK * 2) + c * 16;
            cp16(dst, (const char*)(hl ? (const void*)g_xl : (const void*)g_xh) + src);
        } else {
            int j = i - 1024; int hl = j >> 10;
            int t = j & 1023; int r = t >> 2, c = t & 3;
            uint32_t dst = sb + 2 * MM_A_BYTES + hl * MM_B_BYTES + r * MM_ROWB + c * 16;
            long src = (long)(tileN * BN + r) * (K_DIM * 2) + (long)kt * (MM_BK * 2) + c * 16;
            cp16(dst, (const char*)(hl ? (const void*)g_wl : (const void*)g_wh) + src);
        }
    }
    cp_commit();
}
#endif

// ---------------- main GEMM: warp-specialized TMA + tcgen05, 4-stage ring ----------------
__global__ void __launch_bounds__(THREADS, 1) __cluster_dims__(CLUSTER_SZ, 1, 1)
gemm_kernel(float* __restrict__ out,
            const __grid_constant__ CUtensorMap mAh,
            const __grid_constant__ CUtensorMap mAl,
            const __grid_constant__ CUtensorMap mBh,
            const __grid_constant__ CUtensorMap mBl) {
    extern __shared__ char smem[];
    uint32_t smem_base = smem_u32(smem);
    int tid = threadIdx.x;
    int wid = tid >> 5, lid = tid & 31;
    int bid = blockIdx.x;
    int tileM = bid & 31;   // pair (2k, 2k+1): consecutive tileM, same tileN -> share B
    int tileN = bid >> 5;   // 0..7

#if USE_TC
    // ================= tcgen05 + TMA multicast path =================
    uint32_t rank = ctarank();

    if (wid == 0) TCGEN05_ALLOC(smem_base + SMEM_TMEM_PTR, 256);
    if (tid == 0) {
#pragma unroll
        for (int s = 0; s < NSTAGE; ++s) {
            MBAR_INIT(smem_base + SMEM_FULL(s), 1);   // arrive: producer expect_tx
            MBAR_INIT(smem_base + SMEM_DONE(s), 2);   // arrive: commit-mc from both CTAs
        }
        MBAR_INIT(smem_base + SMEM_FINAL, 2);
    }
    __syncthreads();
    uint32_t tmem;
    asm volatile("ld.shared.b32 %0, [%1];" : "=r"(tmem) : "r"(smem_base + SMEM_TMEM_PTR));

    // Both CTAs' barriers must be live before any multicast TMA targets them.
    CLUSTER_SYNC();

    uint32_t epred = elect_one();

    if (wid == 1 && epred) {
        // ---- producer: 4 TMA per stage, paced by cluster-wide MMA completion ----
        int arow = tileM * BM;
        int brow = tileN * BN + (int)rank * 128;
        for (int kt = 0; kt < TC_NT; ++kt) {
            int s = kt & (NSTAGE - 1);
            uint32_t fb = smem_base + SMEM_FULL(s);
            if (kt >= NSTAGE)
                mbar_wait(smem_base + SMEM_DONE(s), ((kt - NSTAGE) >> 2) & 1);
            MBAR_EXPECT_TX(fb, STAGE_BYTES);
            uint32_t sa = smem_base + TILE_BASE + s * STAGE_BYTES;
            int kx = kt * TC_BK;
            tma2d(sa + STG_A,  &mAh, kx, arow, fb);
            tma2d(sa + STG_AL, &mAl, kx, arow, fb);
            // B halves: each rank loads its 128 rows and multicasts to both CTAs
            tma2d_mc(sa + STG_BH + rank * 8192, &mBh, kx, brow, fb, 3);
            tma2d_mc(sa + STG_BL + rank * 8192, &mBl, kx, brow, fb, 3);
        }
    } else if (wid == 0 && epred) {
        // ---- consumer: 12 MMAs per stage, commit -> done (both CTAs) ----
        for (int kt = 0; kt < TC_NT; ++kt) {
            int s = kt & (NSTAGE - 1);
            mbar_wait(smem_base + SMEM_FULL(s), (kt >> 2) & 1);

            uint32_t sa  = smem_base + TILE_BASE + s * STAGE_BYTES;
            uint64_t dah = make_desc64(sa + STG_A);
            uint64_t dal = make_desc64(sa + STG_AL);
            uint64_t dbh = make_desc64(sa + STG_BH);
            uint64_t dbl = make_desc64(sa + STG_BL);
#pragma unroll
            for (int ks = 0; ks < 2; ++ks) {               // K=16 per MMA, 2 steps (BK=32)
                uint64_t o = (uint64_t)(ks * 2);           // 32B = 2 desc units
#pragma unroll
                for (int h = 0; h < 2; ++h) {              // two N=128 halves
                    uint64_t bo = o + (uint64_t)h * 512;   // 128 rows * 64B = 8KB = 512 units
                    uint32_t dd = tmem + h * 128;
                    uint32_t acc = (kt > 0) || (ks > 0);
                    mma_bf16_ss(dd, dah + o, dbh + bo, acc);  // hi*hi
                    mma_bf16_ss(dd, dah + o, dbl + bo, 1u);   // hi*lo
                    mma_bf16_ss(dd, dal + o, dbh + bo, 1u);   // lo*hi
                }
            }
            TCGEN05_COMMIT_MC(smem_base + SMEM_DONE(s), 3);
        }
        TCGEN05_COMMIT_MC(smem_base + SMEM_FINAL, 3);      // tracks ALL prior MMAs
    }

    // Everyone: wait for all MMAs in BOTH cluster CTAs (count=2, first phase).
    mbar_wait(smem_base + SMEM_FINAL, 0);
    TCGEN05_FENCE_AFTER();

    // Epilogue: 16 warps. warp w -> TMEM lanes (w%4)*32 (its subpartition), cols (w/4)*64
    {
        int rrow  = (wid & 3) * 32 + lid;
        long gm   = (long)tileM * BM + rrow;
        int cbase = (wid >> 2) * 64;
#pragma unroll
        for (int cc = 0; cc < 2; ++cc) {
            uint32_t d[32];
            TCGEN05_LD_X32(d, tmem + cbase + cc * 32);
            TCGEN05_WAIT_LD();
            int gc = tileN * BN + cbase + cc * 32;
            const float4* bp = (const float4*)(g_bias + gc);
            float4* op = (float4*)(out + gm * M_DIM + gc);
#pragma unroll
            for (int q = 0; q < 8; ++q) {
                float4 b = bp[q];
                float4 o;
                o.x = tanhf(__uint_as_float(d[q * 4 + 0]) + b.x);
                o.y = tanhf(__uint_as_float(d[q * 4 + 1]) + b.y);
                o.z = tanhf(__uint_as_float(d[q * 4 + 2]) + b.z);
                o.w = tanhf(__uint_as_float(d[q * 4 + 3]) + b.w);
                op[q] = o;
            }
        }
        TCGEN05_FENCE_BEFORE();
    }

    __syncthreads();
    if (tid == 0) {
#pragma unroll
        for (int s = 0; s < NSTAGE; ++s) {
            MBAR_INVAL(smem_base + SMEM_FULL(s));
            MBAR_INVAL(smem_base + SMEM_DONE(s));
        }
        MBAR_INVAL(smem_base + SMEM_FINAL);
    }
    __syncthreads();
    if (wid == 0) TCGEN05_DEALLOC(tmem, 256);
    // No CTA exits while a peer's multicast targeting this CTA could be in flight.
    CLUSTER_SYNC();

#else
    // ================= HMMA fallback (base-PTX legal; never runs on GB300) =================
    int wr = wid & 3;
    int wc = wid >> 2;

    float acc[2][8][4];
#pragma unroll
    for (int mt = 0; mt < 2; ++mt)
#pragma unroll
        for (int nt = 0; nt < 8; ++nt)
#pragma unroll
            for (int q = 0; q < 4; ++q) acc[mt][nt][q] = 0.0f;

    load_tile_mm(smem_base, 0, 0, tileM, tileN, tid);
    load_tile_mm(smem_base, 1, 1, tileM, tileN, tid);
    load_tile_mm(smem_base, 2, 2, tileM, tileN, tid);

    const int lrow = lid & 15;
    const int lk16b = (lid >> 4) * 16;

    for (int kt = 0; kt < MM_NT; ++kt) {
        asm volatile("cp.async.wait_group 2;" ::: "memory");
        __syncthreads();

        int s = kt % MM_STAGES;
        uint32_t sb  = smem_base + TILE_BASE + s * MM_STAGE;
        uint32_t sAh = sb;
        uint32_t sAl = sb + MM_A_BYTES;
        uint32_t sBh = sb + 2 * MM_A_BYTES;
        uint32_t sBl = sb + 2 * MM_A_BYTES + MM_B_BYTES;

#pragma unroll
        for (int k16 = 0; k16 < 2; ++k16) {
            uint32_t koff = k16 * 32 + lk16b;
            uint32_t aoff = (uint32_t)(wr * 32 + lrow) * MM_ROWB + koff;
            uint32_t boff = (uint32_t)(wc * 64 + lrow) * MM_ROWB + koff;

            uint32_t ah[2][4], bh[4][4];
            ldsm4(ah[0], sAh + aoff);
            ldsm4(ah[1], sAh + aoff + 16 * MM_ROWB);
#pragma unroll
            for (int g = 0; g < 4; ++g) ldsm4(bh[g], sBh + boff + g * 16 * MM_ROWB);

#pragma unroll
            for (int mt = 0; mt < 2; ++mt)
#pragma unroll
                for (int nt = 0; nt < 8; ++nt)
                    mma16816(acc[mt][nt], ah[mt], bh[nt >> 1][nt & 1], bh[nt >> 1][(nt & 1) + 2]);

            uint32_t al[2][4];
            ldsm4(al[0], sAl + aoff);
            ldsm4(al[1], sAl + aoff + 16 * MM_ROWB);
#pragma unroll
            for (int mt = 0; mt < 2; ++mt)
#pragma unroll
                for (int nt = 0; nt < 8; ++nt)
                    mma16816(acc[mt][nt], al[mt], bh[nt >> 1][nt & 1], bh[nt >> 1][(nt & 1) + 2]);

            uint32_t bl[4][4];
#pragma unroll
            for (int g = 0; g < 4; ++g) ldsm4(bl[g], sBl + boff + g * 16 * MM_ROWB);
#pragma unroll
            for (int mt = 0; mt < 2; ++mt)
#pragma unroll
                for (int nt = 0; nt < 8; ++nt)
                    mma16816(acc[mt][nt], ah[mt], bl[nt >> 1][nt & 1], bl[nt >> 1][(nt & 1) + 2]);
        }

        __syncthreads();
        if (kt + MM_STAGES < MM_NT)
            load_tile_mm(smem_base, s, kt + MM_STAGES, tileM, tileN, tid);
    }

    {
        int r0 = tileM * BM + wr * 32 + (lid >> 2);
        int c0 = tileN * BN + wc * 64 + (lid & 3) * 2;
#pragma unroll
        for (int mt = 0; mt < 2; ++mt) {
#pragma unroll
            for (int nt = 0; nt < 8; ++nt) {
                int row = r0 + mt * 16;
                int col = c0 + nt * 8;
                float2 bv = *(const float2*)(g_bias + col);
                float2 o0, o1;
                o0.x = tanhf(acc[mt][nt][0] + bv.x);
                o0.y = tanhf(acc[mt][nt][1] + bv.y);
                o1.x = tanhf(acc[mt][nt][2] + bv.x);
                o1.y = tanhf(acc[mt][nt][3] + bv.y);
                *(float2*)(out + (long)row * M_DIM + col) = o0;
                *(float2*)(out + (long)(row + 8) * M_DIM + col) = o1;
            }
        }
    }
#endif
}

// ---------------- host: tensormap creation via driver entry point ----------------
typedef CUresult (*EncodeTiledFn)(
    CUtensorMap*, CUtensorMapDataType, cuuint32_t, void*,
    const cuuint64_t*, const cuuint64_t*, const cuuint32_t*, const cuuint32_t*,
    CUtensorMapInterleave, CUtensorMapSwizzle, CUtensorMapL2promotion, CUtensorMapFloatOOBfill);

static void make_map(EncodeTiledFn enc, CUtensorMap* m, void* base, unsigned long long rows) {
    cuuint64_t dims[2]    = {(cuuint64_t)K_DIM, (cuuint64_t)rows};
    cuuint64_t strides[1] = {(cuuint64_t)K_DIM * 2};           // bytes between rows
    cuuint32_t box[2]     = {32, 128};                         // 64B x 128 rows (SW64)
    cuuint32_t es[2]      = {1, 1};
    enc(m, CU_TENSOR_MAP_DATA_TYPE_BFLOAT16, 2, base, dims, strides, box, es,
        CU_TENSOR_MAP_INTERLEAVE_NONE, CU_TENSOR_MAP_SWIZZLE_64B,
        CU_TENSOR_MAP_L2_PROMOTION_L2_128B, CU_TENSOR_MAP_FLOAT_OOB_FILL_NONE);
}

extern "C" void kernel_launch(void* const* d_in, const int* in_sizes, int n_in,
                              void* d_out, int out_size) {
    const float* x  = (const float*)d_in[0];
    const float* E  = (const float*)d_in[1];
    // d_in[2] = eternal_biases: unused by the reference as well
    const float* W  = (const float*)d_in[3];
    const float* cb = (const float*)d_in[4];
    float* out = (float*)d_out;

    // tensormaps (host-side; recreated per call — deterministic, no device work)
    EncodeTiledFn enc = nullptr;
    cudaDriverEntryPointQueryResult qr;
    cudaGetDriverEntryPointByVersion("cuTensorMapEncodeTiled", (void**)&enc, 12000,
                                     cudaEnableDefault, &qr);
    void *pxh, *pxl, *pwh, *pwl;
    cudaGetSymbolAddress(&pxh, g_xh);
    cudaGetSymbolAddress(&pxl, g_xl);
    cudaGetSymbolAddress(&pwh, g_wh);
    cudaGetSymbolAddress(&pwl, g_wl);
    CUtensorMap mAh, mAl, mBh, mBl;
    make_map(enc, &mAh, pxh, B_DIM);
    make_map(enc, &mAl, pxl, B_DIM);
    make_map(enc, &mBh, pwh, M_DIM);
    make_map(enc, &mBl, pwl, M_DIM);

    cudaFuncSetAttribute(gemm_kernel, cudaFuncAttributeMaxDynamicSharedMemorySize, SMEM_TOTAL);

    prep_kernel<<<PREP_X_BLOCKS + PREP_W_BLOCKS + PREP_P_BLOCKS, 256>>>(x, W, E, cb);
    gemm_kernel<<<(B_DIM / BM) * (M_DIM / BN), THREADS, SMEM_TOTAL>>>(out, mAh, mAl, mBh, mBl);
}